// round 6
// baseline (speedup 1.0000x reference)
#include <cuda_runtime.h>
#include <cuda_bf16.h>
#include <math.h>
#include <stdint.h>

#define B_   4
#define N_   2048
#define KD_  129
#define H_   8
#define DO_  64
#define AD_  65
#define BH_  (B_*H_)
#define EPS_ 1e-7f
#define MUP_ 68
#define KP_  144

// ---------------- scratch ----------------------------------------------------
__device__ __nv_bfloat16 g_Xb[B_*N_*KP_];
__device__ __nv_bfloat16 g_Wb[24*DO_*KP_];
__device__ __nv_bfloat16 g_Qb[BH_*N_*64];
__device__ __nv_bfloat16 g_Kb[BH_*N_*64];
__device__ float         g_Q0[BH_*N_];
__device__ float         g_K0[BH_*N_];
__device__ __nv_bfloat16 g_Vt[BH_*72*N_];
__device__ float         g_Mu[BH_*N_*MUP_];

// ---------------- helpers ----------------------------------------------------
__device__ __forceinline__ uint32_t smem_u32(const void* p) {
    uint32_t a;
    asm("{ .reg .u64 t; cvta.to.shared.u64 t, %1; cvt.u32.u64 %0, t; }" : "=r"(a) : "l"(p));
    return a;
}
__device__ __forceinline__ void cpa16(uint32_t dst, const void* src) {
    asm volatile("cp.async.cg.shared.global [%0], [%1], 16;" :: "r"(dst), "l"(src));
}
#define CP_COMMIT() asm volatile("cp.async.commit_group;" ::: "memory")
#define CP_WAIT0()  asm volatile("cp.async.wait_group 0;" ::: "memory")
#define CP_WAIT2()  asm volatile("cp.async.wait_group 2;" ::: "memory")

__device__ __forceinline__ void mma16816(float* d,
    uint32_t a0, uint32_t a1, uint32_t a2, uint32_t a3,
    uint32_t b0, uint32_t b1)
{
    asm volatile("mma.sync.aligned.m16n8k16.row.col.f32.bf16.bf16.f32 "
        "{%0,%1,%2,%3}, {%4,%5,%6,%7}, {%8,%9}, {%0,%1,%2,%3};"
        : "+f"(d[0]), "+f"(d[1]), "+f"(d[2]), "+f"(d[3])
        : "r"(a0), "r"(a1), "r"(a2), "r"(a3), "r"(b0), "r"(b1));
}
__device__ __forceinline__ float ex2f(float x) {
    float r; asm("ex2.approx.ftz.f32 %0, %1;" : "=f"(r) : "f"(x)); return r;
}
__device__ __forceinline__ uint32_t bf2(float lo, float hi) {
    uint32_t r; asm("cvt.rn.bf16x2.f32 %0, %1, %2;" : "=r"(r) : "f"(hi), "f"(lo)); return r;
}

// ---------------- prep --------------------------------------------------------
__global__ __launch_bounds__(256) void prep_kernel(
    const float* __restrict__ x,
    const float* __restrict__ Wq, const float* __restrict__ Wk,
    const float* __restrict__ Wv)
{
    const int nt = gridDim.x * 256;
    const int t0 = blockIdx.x * 256 + threadIdx.x;

    for (int i = t0; i < B_*N_*KP_; i += nt) {
        int bn = i / KP_, c = i - bn * KP_;
        g_Xb[i] = __float2bfloat16_rn(c < KD_ ? x[(size_t)bn * KD_ + c] : 0.f);
    }
    for (int i = t0; i < 24*DO_*KP_; i += nt) {
        int idx = i / (DO_*KP_);
        int r   = i - idx * (DO_*KP_);
        int d   = r / KP_, k = r - d * KP_;
        int m = idx >> 3, h = idx & 7;
        const float* W = (m == 0 ? Wq : (m == 1 ? Wk : Wv)) + h * KD_ * DO_;
        g_Wb[i] = __float2bfloat16_rn(k < KD_ ? W[k * DO_ + d] : 0.f);
    }
    for (int i = t0; i < BH_*7*N_; i += nt) {
        int bh = i / (7*N_);
        int r  = i - bh * (7*N_);
        g_Vt[(size_t)bh * 72 * N_ + (size_t)(65 + r / N_) * N_ + (r % N_)] =
            __float2bfloat16_rn(0.f);
    }
}

// ---------------- projection (mma.sync, round-4 proven) -----------------------
#define PX_ST 76
#define PROJ_XS_B (128*PX_ST*4)
#define PROJ_WS_B (64*PX_ST*4)
#define PROJ_SMEM (PROJ_XS_B + PROJ_WS_B)
#define TS_ST 136

__global__ __launch_bounds__(256, 2) void proj_kernel(
    const float* __restrict__ bq, const float* __restrict__ bk,
    const float* __restrict__ bv)
{
    extern __shared__ char smem[];
    const uint32_t sb = smem_u32(smem);
    const int tid = threadIdx.x, wid = tid >> 5, lane = tid & 31;
    const int n0 = blockIdx.x * 128;
    const int h  = blockIdx.y & 7;
    const int m  = blockIdx.y >> 3;
    const int b  = blockIdx.z;
    const int bh = b * H_ + h;

    const __nv_bfloat16* Xg = g_Xb + (size_t)b * N_ * KP_;
    const __nv_bfloat16* Wg = g_Wb + (size_t)blockIdx.y * DO_ * KP_;
    const float* bias = (m == 0 ? bq : (m == 1 ? bk : bv)) + h * DO_;

    for (int i = tid; i < 128 * 18; i += 256) {
        int r = i / 18, c = i - r * 18;
        cpa16(sb + r * (PX_ST*4) + c * 16, Xg + (size_t)(n0 + r) * KP_ + c * 8);
    }
    for (int i = tid; i < 64 * 18; i += 256) {
        int r = i / 18, c = i - r * 18;
        cpa16(sb + PROJ_XS_B + r * (PX_ST*4) + c * 16, Wg + (size_t)r * KP_ + c * 8);
    }
    CP_COMMIT();
    CP_WAIT0();
    __syncthreads();

    const int r0 = wid * 16;
    const int lq = lane >> 2, lm = lane & 3;
    const uint32_t* XS = (const uint32_t*)smem;
    const uint32_t* WS = (const uint32_t*)(smem + PROJ_XS_B);

    float o[8][4];
    #pragma unroll
    for (int jt = 0; jt < 8; jt++) {
        float b0v = bias[jt * 8 + 2 * lm];
        float b1v = bias[jt * 8 + 2 * lm + 1];
        o[jt][0] = b0v; o[jt][1] = b1v; o[jt][2] = b0v; o[jt][3] = b1v;
    }

    #pragma unroll
    for (int ks = 0; ks < 9; ks++) {
        const int dw = ks * 8 + lm;
        uint32_t a0 = XS[(r0 + lq) * PX_ST + dw];
        uint32_t a1 = XS[(r0 + lq + 8) * PX_ST + dw];
        uint32_t a2 = XS[(r0 + lq) * PX_ST + dw + 4];
        uint32_t a3 = XS[(r0 + lq + 8) * PX_ST + dw + 4];
        #pragma unroll
        for (int jt = 0; jt < 8; jt++) {
            uint32_t b0 = WS[(jt * 8 + lq) * PX_ST + dw];
            uint32_t b1 = WS[(jt * 8 + lq) * PX_ST + dw + 4];
            mma16816(o[jt], a0, a1, a2, a3, b0, b1);
        }
    }

    float rs0 = 0.f, rs1 = 0.f;
    #pragma unroll
    for (int jt = 0; jt < 8; jt++) {
        rs0 += o[jt][0]*o[jt][0] + o[jt][1]*o[jt][1];
        rs1 += o[jt][2]*o[jt][2] + o[jt][3]*o[jt][3];
    }
    rs0 += __shfl_xor_sync(0xffffffffu, rs0, 1);
    rs0 += __shfl_xor_sync(0xffffffffu, rs0, 2);
    rs1 += __shfl_xor_sync(0xffffffffu, rs1, 1);
    rs1 += __shfl_xor_sync(0xffffffffu, rs1, 2);
    const float t0v = sqrtf(1.0f + rs0);
    const float t1v = sqrtf(1.0f + rs1);

    const int nA = n0 + r0 + lq, nB = nA + 8;

    if (m < 2) {
        __nv_bfloat16* gb = (m == 0 ? g_Qb : g_Kb) + (size_t)bh * N_ * 64;
        float*         g0 = (m == 0 ? g_Q0 : g_K0) + (size_t)bh * N_;
        #pragma unroll
        for (int jt = 0; jt < 8; jt++) {
            *(uint32_t*)(gb + (size_t)nA * 64 + jt * 8 + 2 * lm) = bf2(o[jt][0], o[jt][1]);
            *(uint32_t*)(gb + (size_t)nB * 64 + jt * 8 + 2 * lm) = bf2(o[jt][2], o[jt][3]);
        }
        if (lm == 0) { g0[nA] = t0v; g0[nB] = t1v; }
    } else {
        __syncthreads();
        __nv_bfloat16* Ts = (__nv_bfloat16*)(smem + PROJ_XS_B);
        const int rA = r0 + lq, rB = rA + 8;
        #pragma unroll
        for (int jt = 0; jt < 8; jt++) {
            int c0 = jt * 8 + 2 * lm;
            Ts[(c0 + 1) * TS_ST + rA] = __float2bfloat16_rn(o[jt][0]);
            Ts[(c0 + 2) * TS_ST + rA] = __float2bfloat16_rn(o[jt][1]);
            Ts[(c0 + 1) * TS_ST + rB] = __float2bfloat16_rn(o[jt][2]);
            Ts[(c0 + 2) * TS_ST + rB] = __float2bfloat16_rn(o[jt][3]);
        }
        if (lm == 0) { Ts[rA] = __float2bfloat16_rn(t0v); Ts[rB] = __float2bfloat16_rn(t1v); }
        __syncthreads();

        __nv_bfloat16* gv = g_Vt + (size_t)bh * 72 * N_;
        for (int i = tid; i < 65 * 16; i += 256) {
            int a = i >> 4, ch = i & 15;
            uint4 v = *(const uint4*)(Ts + a * TS_ST + ch * 8);
            *(uint4*)(gv + (size_t)a * N_ + n0 + ch * 8) = v;
        }
    }
}

// ---------------- attention: 32 q-rows x 32 keys per warp ---------------------
// 8 warps: rg = wid&3 (rows rg*32..+31), kh = wid>>2 (key half of 64-key tile)
// 4-slot / 3-deep cp.async ring. Q fragments hoisted to registers.
#define OFF_Q    0                       // 128 rows x 144B = 18432
#define OFF_AQ0  18432                   // 512
#define OFF_ST   18944
#define STG_V    9216
#define STG_K0   19584
#define STG_SZ   19840
#define ATTN_SMEM (OFF_ST + 4*STG_SZ)    // 98304
#define EXW 76                           // epilogue exchange row stride (words)

__global__ __launch_bounds__(256, 1) void attn_kernel(const float* __restrict__ scale_p)
{
    extern __shared__ char smem[];
    const uint32_t sb = smem_u32(smem);
    const int tid = threadIdx.x, wid = tid >> 5, lane = tid & 31;
    const int bh  = blockIdx.y;
    const int q0g = blockIdx.x * 128;

    const __nv_bfloat16* Qg = g_Qb + (size_t)bh * N_ * 64;
    const __nv_bfloat16* Kg = g_Kb + (size_t)bh * N_ * 64;
    const __nv_bfloat16* Vg = g_Vt + (size_t)bh * 72 * N_;
    const float* k0g = g_K0 + (size_t)bh * N_;

    const float a2c = 2.0f * 1.4426950408889634f / (scale_p[0] + EPS_);

    // prologue: group0 = Q + stage0, group1 = stage1, group2 = stage2
    // Q rows are 128 B = 8 x 16B chunks, stored at 144 B stride.
    for (int i = tid; i < 1024; i += 256) {
        int r = i >> 3, c = i & 7;
        cpa16(sb + OFF_Q + r * 144 + c * 16, Qg + (size_t)(q0g + r) * 64 + c * 8);
    }
    #pragma unroll
    for (int st = 0; st < 3; st++) {
        const int j0 = st * 64;
        const uint32_t stg = sb + OFF_ST + st * STG_SZ;
        for (int i = tid; i < 512; i += 256) {
            int r = i >> 3, c = i & 7;
            cpa16(stg + r * 144 + c * 16, Kg + (size_t)(j0 + r) * 64 + c * 8);
        }
        for (int i = tid; i < 576; i += 256) {
            int a = i >> 3, c = i & 7;
            cpa16(stg + STG_V + a * 144 + c * 16, Vg + (size_t)a * N_ + j0 + c * 8);
        }
        if (tid < 16) cpa16(stg + STG_K0 + tid * 16, k0g + j0 + tid * 4);
        CP_COMMIT();
    }
    if (tid < 128)
        ((float*)(smem + OFF_AQ0))[tid] = a2c * g_Q0[(size_t)bh * N_ + q0g + tid];

    CP_WAIT2();          // completes group0 (Q + stage0)
    __syncthreads();     // Q, aq0, stage0 visible to all

    const int rg = wid & 3, kh = wid >> 2;
    const int lq = lane >> 2, lm = lane & 3;
    const int khk = kh * 32;

    // hoist Q fragments: qf[ks][mg][4]
    uint32_t qf[4][2][4];
    {
        const uint32_t* QSw = (const uint32_t*)(smem + OFF_Q);
        #pragma unroll
        for (int ks = 0; ks < 4; ks++) {
            const int dw = ks * 8 + lm;
            #pragma unroll
            for (int mg = 0; mg < 2; mg++) {
                const int rA = rg * 32 + mg * 16 + lq;
                qf[ks][mg][0] = QSw[rA * 36 + dw];
                qf[ks][mg][1] = QSw[(rA + 8) * 36 + dw];
                qf[ks][mg][2] = QSw[rA * 36 + dw + 4];
                qf[ks][mg][3] = QSw[(rA + 8) * 36 + dw + 4];
            }
        }
    }
    float aq[2][2];
    #pragma unroll
    for (int mg = 0; mg < 2; mg++) {
        aq[mg][0] = ((const float*)(smem + OFF_AQ0))[rg * 32 + mg * 16 + lq];
        aq[mg][1] = ((const float*)(smem + OFF_AQ0))[rg * 32 + mg * 16 + lq + 8];
    }

    float o[2][9][4];
    #pragma unroll
    for (int mg = 0; mg < 2; mg++)
        #pragma unroll
        for (int at = 0; at < 9; at++)
            #pragma unroll
            for (int c = 0; c < 4; c++) o[mg][at][c] = 0.f;
    float lsum[2][2] = {{0.f,0.f},{0.f,0.f}};

    for (int t = 0; t < 32; t++) {
        if (t) { CP_WAIT2(); __syncthreads(); }
        const uint32_t stg = OFF_ST + (t & 3) * STG_SZ;
        const uint32_t* KS  = (const uint32_t*)(smem + stg);
        const uint32_t* VS  = (const uint32_t*)(smem + stg + STG_V);
        const float*    k0s = (const float*)(smem + stg + STG_K0);

        // S = Q.K^T : 32 rows x 32 keys per warp
        float s[2][4][4];
        #pragma unroll
        for (int mg = 0; mg < 2; mg++)
            #pragma unroll
            for (int jt = 0; jt < 4; jt++)
                #pragma unroll
                for (int c = 0; c < 4; c++) s[mg][jt][c] = 0.f;

        #pragma unroll
        for (int ks = 0; ks < 4; ks++) {
            const int dw = ks * 8 + lm;
            #pragma unroll
            for (int jt = 0; jt < 4; jt++) {
                uint32_t b0 = KS[(khk + jt * 8 + lq) * 36 + dw];
                uint32_t b1 = KS[(khk + jt * 8 + lq) * 36 + dw + 4];
                mma16816(s[0][jt], qf[ks][0][0], qf[ks][0][1], qf[ks][0][2], qf[ks][0][3], b0, b1);
                mma16816(s[1][jt], qf[ks][1][0], qf[ks][1][1], qf[ks][1][2], qf[ks][1][3], b0, b1);
            }
        }

        // softmax
        uint32_t pf[2][4][2];
        #pragma unroll
        for (int jt = 0; jt < 4; jt++) {
            const float k0a = k0s[khk + jt * 8 + lm * 2];
            const float k0b = k0s[khk + jt * 8 + lm * 2 + 1];
            #pragma unroll
            for (int mg = 0; mg < 2; mg++) {
                float p0 = ex2f(fmaf(a2c, s[mg][jt][0], -aq[mg][0] * k0a));
                float p1 = ex2f(fmaf(a2c, s[mg][jt][1], -aq[mg][0] * k0b));
                float p2 = ex2f(fmaf(a2c, s[mg][jt][2], -aq[mg][1] * k0a));
                float p3 = ex2f(fmaf(a2c, s[mg][jt][3], -aq[mg][1] * k0b));
                lsum[mg][0] += p0 + p1;
                lsum[mg][1] += p2 + p3;
                pf[mg][jt][0] = bf2(p0, p1);
                pf[mg][jt][1] = bf2(p2, p3);
            }
        }

        // O += P.V
        #pragma unroll
        for (int kt = 0; kt < 2; kt++) {
            #pragma unroll
            for (int at = 0; at < 9; at++) {
                uint32_t b0 = VS[(at * 8 + lq) * 36 + kh * 16 + kt * 8 + lm];
                uint32_t b1 = VS[(at * 8 + lq) * 36 + kh * 16 + kt * 8 + lm + 4];
                mma16816(o[0][at], pf[0][2*kt][0], pf[0][2*kt][1], pf[0][2*kt+1][0], pf[0][2*kt+1][1], b0, b1);
                mma16816(o[1][at], pf[1][2*kt][0], pf[1][2*kt][1], pf[1][2*kt+1][0], pf[1][2*kt+1][1], b0, b1);
            }
        }

        // prefetch tile t+3 into slot (t+3)&3  (slot of t-1; safe after top sync)
        if (t + 3 < 32) {
            const int j0 = (t + 3) * 64;
            const uint32_t pstg = sb + OFF_ST + ((t + 3) & 3) * STG_SZ;
            for (int i = tid; i < 512; i += 256) {
                int r = i >> 3, c = i & 7;
                cpa16(pstg + r * 144 + c * 16, Kg + (size_t)(j0 + r) * 64 + c * 8);
            }
            for (int i = tid; i < 576; i += 256) {
                int a = i >> 3, c = i & 7;
                cpa16(pstg + STG_V + a * 144 + c * 16, Vg + (size_t)a * N_ + j0 + c * 8);
            }
            if (tid < 16) cpa16(pstg + STG_K0 + tid * 16, k0g + j0 + tid * 4);
        }
        CP_COMMIT();
    }

    // quad-reduce row sums
    #pragma unroll
    for (int mg = 0; mg < 2; mg++)
        #pragma unroll
        for (int hh = 0; hh < 2; hh++) {
            lsum[mg][hh] += __shfl_xor_sync(0xffffffffu, lsum[mg][hh], 1);
            lsum[mg][hh] += __shfl_xor_sync(0xffffffffu, lsum[mg][hh], 2);
        }

    __syncthreads();   // all stage reads done; reuse stage area for exchange
    float* Ex = (float*)(smem + OFF_ST);
    float* Ls = (float*)(smem + OFF_AQ0);

    if (kh == 1) {
        #pragma unroll
        for (int mg = 0; mg < 2; mg++) {
            const int rA = rg * 32 + mg * 16 + lq, rB = rA + 8;
            #pragma unroll
            for (int at = 0; at < 9; at++) {
                const int c = at * 8 + 2 * lm;
                *(float2*)&Ex[rA * EXW + c] = make_float2(o[mg][at][0], o[mg][at][1]);
                *(float2*)&Ex[rB * EXW + c] = make_float2(o[mg][at][2], o[mg][at][3]);
            }
            if (lm == 0) { Ls[rA] = lsum[mg][0]; Ls[rB] = lsum[mg][1]; }
        }
    }
    __syncthreads();

    if (kh == 0) {
        #pragma unroll
        for (int mg = 0; mg < 2; mg++) {
            const int rA = rg * 32 + mg * 16 + lq, rB = rA + 8;
            const float inv0 = 1.0f / (lsum[mg][0] + Ls[rA]);
            const float inv1 = 1.0f / (lsum[mg][1] + Ls[rB]);
            float* mA = g_Mu + ((size_t)bh * N_ + q0g + rA) * MUP_;
            float* mB = g_Mu + ((size_t)bh * N_ + q0g + rB) * MUP_;
            #pragma unroll
            for (int at = 0; at < 9; at++) {
                const int c = at * 8 + 2 * lm;
                float2 eA = *(float2*)&Ex[rA * EXW + c];
                float2 eB = *(float2*)&Ex[rB * EXW + c];
                if (c < 65)     { mA[c]   = (o[mg][at][0] + eA.x) * inv0;
                                  mB[c]   = (o[mg][at][2] + eB.x) * inv1; }
                if (c + 1 < 65) { mA[c+1] = (o[mg][at][1] + eA.y) * inv0;
                                  mB[c+1] = (o[mg][at][3] + eB.y) * inv1; }
            }
        }
    }
}

// ---------------- finalize ----------------------------------------------------
__global__ __launch_bounds__(256) void finalize_kernel(float* __restrict__ out)
{
    const int gw = (blockIdx.x * blockDim.x + threadIdx.x) >> 5;
    const int lane = threadIdx.x & 31;
    if (gw >= B_ * N_) return;
    const int b = gw >> 11, n = gw & (N_ - 1);

    float a0 = 0.f, a1 = 0.f, a2 = 0.f;
    for (int h = 0; h < H_; h++) {
        const float* mu = g_Mu + ((size_t)(b * H_ + h) * N_ + n) * MUP_;
        float m0 = mu[lane];
        float m1 = mu[lane + 32];
        float m2 = (lane == 0) ? mu[64] : 0.f;
        float ss = m0 * m0 + m1 * m1 + m2 * m2;
        #pragma unroll
        for (int o = 16; o; o >>= 1) ss += __shfl_xor_sync(0xffffffffu, ss, o);
        float mu0 = __shfl_sync(0xffffffffu, m0, 0);
        float neg = 2.0f * mu0 * mu0 - ss;
        float inv = rsqrtf(fmaxf(neg, EPS_)) * (1.0f / H_);
        a0 += m0 * inv; a1 += m1 * inv; a2 += m2 * inv;
    }
    float ss = a0 * a0 + a1 * a1 + a2 * a2;
    #pragma unroll
    for (int o = 16; o; o >>= 1) ss += __shfl_xor_sync(0xffffffffu, ss, o);
    float av0 = __shfl_sync(0xffffffffu, a0, 0);
    float neg = 2.0f * av0 * av0 - ss;
    float inv2 = rsqrtf(fmaxf(neg, EPS_));
    float sp0 = a0 * inv2, sp1 = a1 * inv2, sp2 = a2 * inv2;

    float ssp = sp1 * sp1 + ((lane == 0) ? sp2 * sp2 : sp0 * sp0);
    #pragma unroll
    for (int o = 16; o; o >>= 1) ssp += __shfl_xor_sync(0xffffffffu, ssp, o);
    float t = sqrtf(1.0f + ssp);

    float* o_ = out + ((size_t)b * N_ + n) * AD_;
    o_[lane]      = (lane == 0) ? t : sp0;
    o_[lane + 32] = sp1;
    if (lane == 0) o_[64] = sp2;
}

// ---------------- launch ------------------------------------------------------
extern "C" void kernel_launch(void* const* d_in, const int* in_sizes, int n_in,
                              void* d_out, int out_size)
{
    const float* x     = (const float*)d_in[0];
    const float* Wq    = (const float*)d_in[1];
    const float* Wk    = (const float*)d_in[2];
    const float* Wv    = (const float*)d_in[3];
    const float* bq    = (const float*)d_in[4];
    const float* bk    = (const float*)d_in[5];
    const float* bv    = (const float*)d_in[6];
    const float* scale = (const float*)d_in[7];
    float* out = (float*)d_out;

    cudaFuncSetAttribute(proj_kernel, cudaFuncAttributeMaxDynamicSharedMemorySize, PROJ_SMEM);
    cudaFuncSetAttribute(attn_kernel, cudaFuncAttributeMaxDynamicSharedMemorySize, ATTN_SMEM);

    prep_kernel<<<1024, 256>>>(x, Wq, Wk, Wv);
    proj_kernel<<<dim3(N_/128, 24, B_), 256, PROJ_SMEM>>>(bq, bk, bv);
    attn_kernel<<<dim3(N_/128, BH_), 256, ATTN_SMEM>>>(scale);
    finalize_kernel<<<(B_*N_*32 + 255)/256, 256>>>(out);
}

// round 7
// speedup vs baseline: 1.1045x; 1.1045x over previous
#include <cuda_runtime.h>
#include <cuda_bf16.h>
#include <math.h>
#include <stdint.h>

#define B_   4
#define N_   2048
#define KD_  129
#define H_   8
#define DO_  64
#define AD_  65
#define BH_  (B_*H_)
#define EPS_ 1e-7f
#define MUP_ 68
#define KP_  144

// ---------------- scratch ----------------------------------------------------
__device__ __nv_bfloat16 g_Xb[B_*N_*KP_];
__device__ __nv_bfloat16 g_Wb[24*DO_*KP_];
__device__ __nv_bfloat16 g_Qb[BH_*N_*64];
__device__ __nv_bfloat16 g_Kb[BH_*N_*64];
__device__ float         g_Q0[BH_*N_];
__device__ float         g_KV0[BH_*N_*2];        // (k_time, v_time) fp32 pairs
__device__ __nv_bfloat16 g_Vt[BH_*64*N_];        // V^T spatial only [bh][64][N]
__device__ float         g_Mu[BH_*N_*MUP_];

// ---------------- helpers ----------------------------------------------------
__device__ __forceinline__ uint32_t smem_u32(const void* p) {
    uint32_t a;
    asm("{ .reg .u64 t; cvta.to.shared.u64 t, %1; cvt.u32.u64 %0, t; }" : "=r"(a) : "l"(p));
    return a;
}
__device__ __forceinline__ void cpa16(uint32_t dst, const void* src) {
    asm volatile("cp.async.cg.shared.global [%0], [%1], 16;" :: "r"(dst), "l"(src));
}
#define CP_COMMIT() asm volatile("cp.async.commit_group;" ::: "memory")
#define CP_WAIT0()  asm volatile("cp.async.wait_group 0;" ::: "memory")
#define CP_WAIT2()  asm volatile("cp.async.wait_group 2;" ::: "memory")

__device__ __forceinline__ void mma16816(float* d,
    uint32_t a0, uint32_t a1, uint32_t a2, uint32_t a3,
    uint32_t b0, uint32_t b1)
{
    asm volatile("mma.sync.aligned.m16n8k16.row.col.f32.bf16.bf16.f32 "
        "{%0,%1,%2,%3}, {%4,%5,%6,%7}, {%8,%9}, {%0,%1,%2,%3};"
        : "+f"(d[0]), "+f"(d[1]), "+f"(d[2]), "+f"(d[3])
        : "r"(a0), "r"(a1), "r"(a2), "r"(a3), "r"(b0), "r"(b1));
}
__device__ __forceinline__ void ldm_x4(uint32_t& r0, uint32_t& r1,
                                       uint32_t& r2, uint32_t& r3, uint32_t a)
{
    asm volatile("ldmatrix.sync.aligned.m8n8.x4.shared.b16 {%0,%1,%2,%3}, [%4];"
        : "=r"(r0), "=r"(r1), "=r"(r2), "=r"(r3) : "r"(a));
}
__device__ __forceinline__ float ex2f(float x) {
    float r; asm("ex2.approx.ftz.f32 %0, %1;" : "=f"(r) : "f"(x)); return r;
}
__device__ __forceinline__ uint32_t bf2(float lo, float hi) {
    uint32_t r; asm("cvt.rn.bf16x2.f32 %0, %1, %2;" : "=r"(r) : "f"(hi), "f"(lo)); return r;
}

// ---------------- prep --------------------------------------------------------
__global__ __launch_bounds__(256) void prep_kernel(
    const float* __restrict__ x,
    const float* __restrict__ Wq, const float* __restrict__ Wk,
    const float* __restrict__ Wv)
{
    const int nt = gridDim.x * 256;
    const int t0 = blockIdx.x * 256 + threadIdx.x;

    for (int i = t0; i < B_*N_*KP_; i += nt) {
        int bn = i / KP_, c = i - bn * KP_;
        g_Xb[i] = __float2bfloat16_rn(c < KD_ ? x[(size_t)bn * KD_ + c] : 0.f);
    }
    for (int i = t0; i < 24*DO_*KP_; i += nt) {
        int idx = i / (DO_*KP_);
        int r   = i - idx * (DO_*KP_);
        int d   = r / KP_, k = r - d * KP_;
        int m = idx >> 3, h = idx & 7;
        const float* W = (m == 0 ? Wq : (m == 1 ? Wk : Wv)) + h * KD_ * DO_;
        g_Wb[i] = __float2bfloat16_rn(k < KD_ ? W[k * DO_ + d] : 0.f);
    }
}

// ---------------- projection (mma.sync, round-4 proven) -----------------------
#define PX_ST 76
#define PROJ_XS_B (128*PX_ST*4)
#define PROJ_WS_B (64*PX_ST*4)
#define PROJ_SMEM (PROJ_XS_B + PROJ_WS_B)
#define TS_ST 136

__global__ __launch_bounds__(256, 2) void proj_kernel(
    const float* __restrict__ bq, const float* __restrict__ bk,
    const float* __restrict__ bv)
{
    extern __shared__ char smem[];
    const uint32_t sb = smem_u32(smem);
    const int tid = threadIdx.x, wid = tid >> 5, lane = tid & 31;
    const int n0 = blockIdx.x * 128;
    const int h  = blockIdx.y & 7;
    const int m  = blockIdx.y >> 3;
    const int b  = blockIdx.z;
    const int bh = b * H_ + h;

    const __nv_bfloat16* Xg = g_Xb + (size_t)b * N_ * KP_;
    const __nv_bfloat16* Wg = g_Wb + (size_t)blockIdx.y * DO_ * KP_;
    const float* bias = (m == 0 ? bq : (m == 1 ? bk : bv)) + h * DO_;

    for (int i = tid; i < 128 * 18; i += 256) {
        int r = i / 18, c = i - r * 18;
        cpa16(sb + r * (PX_ST*4) + c * 16, Xg + (size_t)(n0 + r) * KP_ + c * 8);
    }
    for (int i = tid; i < 64 * 18; i += 256) {
        int r = i / 18, c = i - r * 18;
        cpa16(sb + PROJ_XS_B + r * (PX_ST*4) + c * 16, Wg + (size_t)r * KP_ + c * 8);
    }
    CP_COMMIT();
    CP_WAIT0();
    __syncthreads();

    const int r0 = wid * 16;
    const int lq = lane >> 2, lm = lane & 3;
    const uint32_t* XS = (const uint32_t*)smem;
    const uint32_t* WS = (const uint32_t*)(smem + PROJ_XS_B);

    float o[8][4];
    #pragma unroll
    for (int jt = 0; jt < 8; jt++) {
        float b0v = bias[jt * 8 + 2 * lm];
        float b1v = bias[jt * 8 + 2 * lm + 1];
        o[jt][0] = b0v; o[jt][1] = b1v; o[jt][2] = b0v; o[jt][3] = b1v;
    }

    #pragma unroll
    for (int ks = 0; ks < 9; ks++) {
        const int dw = ks * 8 + lm;
        uint32_t a0 = XS[(r0 + lq) * PX_ST + dw];
        uint32_t a1 = XS[(r0 + lq + 8) * PX_ST + dw];
        uint32_t a2 = XS[(r0 + lq) * PX_ST + dw + 4];
        uint32_t a3 = XS[(r0 + lq + 8) * PX_ST + dw + 4];
        #pragma unroll
        for (int jt = 0; jt < 8; jt++) {
            uint32_t b0 = WS[(jt * 8 + lq) * PX_ST + dw];
            uint32_t b1 = WS[(jt * 8 + lq) * PX_ST + dw + 4];
            mma16816(o[jt], a0, a1, a2, a3, b0, b1);
        }
    }

    float rs0 = 0.f, rs1 = 0.f;
    #pragma unroll
    for (int jt = 0; jt < 8; jt++) {
        rs0 += o[jt][0]*o[jt][0] + o[jt][1]*o[jt][1];
        rs1 += o[jt][2]*o[jt][2] + o[jt][3]*o[jt][3];
    }
    rs0 += __shfl_xor_sync(0xffffffffu, rs0, 1);
    rs0 += __shfl_xor_sync(0xffffffffu, rs0, 2);
    rs1 += __shfl_xor_sync(0xffffffffu, rs1, 1);
    rs1 += __shfl_xor_sync(0xffffffffu, rs1, 2);
    const float t0v = sqrtf(1.0f + rs0);
    const float t1v = sqrtf(1.0f + rs1);

    const int nA = n0 + r0 + lq, nB = nA + 8;

    if (m < 2) {
        __nv_bfloat16* gb = (m == 0 ? g_Qb : g_Kb) + (size_t)bh * N_ * 64;
        #pragma unroll
        for (int jt = 0; jt < 8; jt++) {
            *(uint32_t*)(gb + (size_t)nA * 64 + jt * 8 + 2 * lm) = bf2(o[jt][0], o[jt][1]);
            *(uint32_t*)(gb + (size_t)nB * 64 + jt * 8 + 2 * lm) = bf2(o[jt][2], o[jt][3]);
        }
        if (lm == 0) {
            if (m == 0) {
                g_Q0[(size_t)bh * N_ + nA] = t0v;
                g_Q0[(size_t)bh * N_ + nB] = t1v;
            } else {
                g_KV0[((size_t)bh * N_ + nA) * 2] = t0v;
                g_KV0[((size_t)bh * N_ + nB) * 2] = t1v;
            }
        }
    } else {
        __syncthreads();
        __nv_bfloat16* Ts = (__nv_bfloat16*)(smem + PROJ_XS_B);
        const int rA = r0 + lq, rB = rA + 8;
        #pragma unroll
        for (int jt = 0; jt < 8; jt++) {
            int c0 = jt * 8 + 2 * lm;
            Ts[c0 * TS_ST + rA]       = __float2bfloat16_rn(o[jt][0]);
            Ts[(c0 + 1) * TS_ST + rA] = __float2bfloat16_rn(o[jt][1]);
            Ts[c0 * TS_ST + rB]       = __float2bfloat16_rn(o[jt][2]);
            Ts[(c0 + 1) * TS_ST + rB] = __float2bfloat16_rn(o[jt][3]);
        }
        if (lm == 0) {
            g_KV0[((size_t)bh * N_ + nA) * 2 + 1] = t0v;
            g_KV0[((size_t)bh * N_ + nB) * 2 + 1] = t1v;
        }
        __syncthreads();

        __nv_bfloat16* gv = g_Vt + (size_t)bh * 64 * N_;
        for (int i = tid; i < 64 * 16; i += 256) {
            int a = i >> 4, ch = i & 15;
            uint4 v = *(const uint4*)(Ts + a * TS_ST + ch * 8);
            *(uint4*)(gv + (size_t)a * N_ + n0 + ch * 8) = v;
        }
    }
}

// ---------------- attention: round-4 tiling + ldmatrix + reg-hoisted Q --------
// 8 warps x (16 q-rows x 64 keys). 4-slot / 3-deep cp.async ring, occ 2.
#define OFF_Q    0                       // 128 x 144B = 18432
#define OFF_AQ0  18432                   // 512
#define OFF_ST   18944
#define STG_V    9216
#define STG_KV0  18432
#define STG_SZ   18944
#define ATTN_SMEM (OFF_ST + 4*STG_SZ)    // 94720

__global__ __launch_bounds__(256, 2) void attn_kernel(const float* __restrict__ scale_p)
{
    extern __shared__ char smem[];
    const uint32_t sb = smem_u32(smem);
    const int tid = threadIdx.x, wid = tid >> 5, lane = tid & 31;
    const int bh  = blockIdx.y;
    const int q0g = blockIdx.x * 128;

    const __nv_bfloat16* Qg = g_Qb + (size_t)bh * N_ * 64;
    const __nv_bfloat16* Kg = g_Kb + (size_t)bh * N_ * 64;
    const __nv_bfloat16* Vg = g_Vt + (size_t)bh * 64 * N_;
    const float* kv0 = g_KV0 + (size_t)bh * N_ * 2;

    const float a2c = 2.0f * 1.4426950408889634f / (scale_p[0] + EPS_);

    // prologue: group0 = Q + stage0, group1 = stage1, group2 = stage2
    for (int i = tid; i < 1024; i += 256) {
        int r = i >> 3, c = i & 7;
        cpa16(sb + OFF_Q + r * 144 + c * 16, Qg + (size_t)(q0g + r) * 64 + c * 8);
    }
    #pragma unroll
    for (int st = 0; st < 3; st++) {
        const int j0 = st * 64;
        const uint32_t stg = sb + OFF_ST + st * STG_SZ;
        for (int i = tid; i < 512; i += 256) {
            int r = i >> 3, c = i & 7;
            cpa16(stg + r * 144 + c * 16, Kg + (size_t)(j0 + r) * 64 + c * 8);
        }
        for (int i = tid; i < 512; i += 256) {
            int a = i >> 3, c = i & 7;
            cpa16(stg + STG_V + a * 144 + c * 16, Vg + (size_t)a * N_ + j0 + c * 8);
        }
        if (tid < 32) cpa16(stg + STG_KV0 + tid * 16, kv0 + (size_t)j0 * 2 + tid * 4);
        CP_COMMIT();
    }
    if (tid < 128)
        ((float*)(smem + OFF_AQ0))[tid] = a2c * g_Q0[(size_t)bh * N_ + q0g + tid];

    CP_WAIT2();
    __syncthreads();

    const int r0 = wid * 16;
    const int lq = lane >> 2, lm = lane & 3;
    // per-lane ldmatrix offset (shared by K and V phases)
    const uint32_t offl =
        (uint32_t)((((lane >> 3) & 2) ? 8 : 0) + (lane & 7)) * 144u
        + (((lane >> 3) & 1) ? 16u : 0u);

    // hoist Q fragments (once)
    uint32_t qf[4][4];
    {
        const uint32_t* QSw = (const uint32_t*)(smem + OFF_Q);
        #pragma unroll
        for (int ks = 0; ks < 4; ks++) {
            const int dw = ks * 8 + lm;
            qf[ks][0] = QSw[(r0 + lq) * 36 + dw];
            qf[ks][1] = QSw[(r0 + lq + 8) * 36 + dw];
            qf[ks][2] = QSw[(r0 + lq) * 36 + dw + 4];
            qf[ks][3] = QSw[(r0 + lq + 8) * 36 + dw + 4];
        }
    }
    const float aq0 = ((const float*)(smem + OFF_AQ0))[r0 + lq];
    const float aq1 = ((const float*)(smem + OFF_AQ0))[r0 + lq + 8];

    float o[8][4];
    #pragma unroll
    for (int at = 0; at < 8; at++)
        #pragma unroll
        for (int c = 0; c < 4; c++) o[at][c] = 0.f;
    float lsum0 = 0.f, lsum1 = 0.f, tac0 = 0.f, tac1 = 0.f;

    for (int t = 0; t < 32; t++) {
        if (t) { CP_WAIT2(); __syncthreads(); }
        const uint32_t stgo = OFF_ST + (t & 3) * STG_SZ;
        const uint32_t ks_base = sb + stgo + offl;
        const uint32_t vs_base = sb + stgo + STG_V + offl;

        // S = Q.K^T : ldmatrix.x4 per (ks, key-16-group)
        float s[8][4];
        #pragma unroll
        for (int jt = 0; jt < 8; jt++)
            #pragma unroll
            for (int c = 0; c < 4; c++) s[jt][c] = 0.f;

        #pragma unroll
        for (int ks = 0; ks < 4; ks++) {
            #pragma unroll
            for (int q = 0; q < 4; q++) {
                uint32_t b0, b1, b2, b3;
                ldm_x4(b0, b1, b2, b3, ks_base + q * 2304 + ks * 32);
                mma16816(s[2*q],   qf[ks][0], qf[ks][1], qf[ks][2], qf[ks][3], b0, b1);
                mma16816(s[2*q+1], qf[ks][0], qf[ks][1], qf[ks][2], qf[ks][3], b2, b3);
            }
        }

        // softmax + fp32 time-channel accumulation
        const float2* kvs = (const float2*)(smem + stgo + STG_KV0);
        uint32_t pf[8][2];
        #pragma unroll
        for (int jt = 0; jt < 8; jt++) {
            const float2 kva = kvs[jt * 8 + 2 * lm];
            const float2 kvb = kvs[jt * 8 + 2 * lm + 1];
            float p0 = ex2f(fmaf(a2c, s[jt][0], -aq0 * kva.x));
            float p1 = ex2f(fmaf(a2c, s[jt][1], -aq0 * kvb.x));
            float p2 = ex2f(fmaf(a2c, s[jt][2], -aq1 * kva.x));
            float p3 = ex2f(fmaf(a2c, s[jt][3], -aq1 * kvb.x));
            lsum0 += p0 + p1;  lsum1 += p2 + p3;
            tac0  = fmaf(p0, kva.y, fmaf(p1, kvb.y, tac0));
            tac1  = fmaf(p2, kva.y, fmaf(p3, kvb.y, tac1));
            pf[jt][0] = bf2(p0, p1);
            pf[jt][1] = bf2(p2, p3);
        }

        // O += P.V : ldmatrix.x4 per (kt, at-pair)
        #pragma unroll
        for (int kt = 0; kt < 4; kt++) {
            const uint32_t A0 = pf[2*kt][0], A1 = pf[2*kt][1];
            const uint32_t A2 = pf[2*kt+1][0], A3 = pf[2*kt+1][1];
            #pragma unroll
            for (int p = 0; p < 4; p++) {
                uint32_t b0, b1, b2, b3;
                ldm_x4(b0, b1, b2, b3, vs_base + p * 2304 + kt * 32);
                mma16816(o[2*p],   A0, A1, A2, A3, b0, b1);
                mma16816(o[2*p+1], A0, A1, A2, A3, b2, b3);
            }
        }

        // prefetch tile t+3
        if (t + 3 < 32) {
            const int j0 = (t + 3) * 64;
            const uint32_t pstg = sb + OFF_ST + ((t + 3) & 3) * STG_SZ;
            for (int i = tid; i < 512; i += 256) {
                int r = i >> 3, c = i & 7;
                cpa16(pstg + r * 144 + c * 16, Kg + (size_t)(j0 + r) * 64 + c * 8);
            }
            for (int i = tid; i < 512; i += 256) {
                int a = i >> 3, c = i & 7;
                cpa16(pstg + STG_V + a * 144 + c * 16, Vg + (size_t)a * N_ + j0 + c * 8);
            }
            if (tid < 32) cpa16(pstg + STG_KV0 + tid * 16, kv0 + (size_t)j0 * 2 + tid * 4);
        }
        CP_COMMIT();
    }

    // quad-reduce sums, normalize, write Mu (each warp owns its 16 rows)
    lsum0 += __shfl_xor_sync(0xffffffffu, lsum0, 1);
    lsum0 += __shfl_xor_sync(0xffffffffu, lsum0, 2);
    lsum1 += __shfl_xor_sync(0xffffffffu, lsum1, 1);
    lsum1 += __shfl_xor_sync(0xffffffffu, lsum1, 2);
    tac0  += __shfl_xor_sync(0xffffffffu, tac0, 1);
    tac0  += __shfl_xor_sync(0xffffffffu, tac0, 2);
    tac1  += __shfl_xor_sync(0xffffffffu, tac1, 1);
    tac1  += __shfl_xor_sync(0xffffffffu, tac1, 2);
    const float inv0 = 1.0f / lsum0;
    const float inv1 = 1.0f / lsum1;

    float* mA = g_Mu + ((size_t)bh * N_ + q0g + r0 + lq) * MUP_;
    float* mB = mA + 8 * MUP_;
    #pragma unroll
    for (int at = 0; at < 8; at++) {
        const int c = at * 8 + 2 * lm;
        mA[c + 1] = o[at][0] * inv0;  mA[c + 2] = o[at][1] * inv0;
        mB[c + 1] = o[at][2] * inv1;  mB[c + 2] = o[at][3] * inv1;
    }
    if (lm == 0) { mA[0] = tac0 * inv0; mB[0] = tac1 * inv1; }
}

// ---------------- finalize ----------------------------------------------------
__global__ __launch_bounds__(256) void finalize_kernel(float* __restrict__ out)
{
    const int gw = (blockIdx.x * blockDim.x + threadIdx.x) >> 5;
    const int lane = threadIdx.x & 31;
    if (gw >= B_ * N_) return;
    const int b = gw >> 11, n = gw & (N_ - 1);

    float a0 = 0.f, a1 = 0.f, a2 = 0.f;
    for (int h = 0; h < H_; h++) {
        const float* mu = g_Mu + ((size_t)(b * H_ + h) * N_ + n) * MUP_;
        float m0 = mu[lane];
        float m1 = mu[lane + 32];
        float m2 = (lane == 0) ? mu[64] : 0.f;
        float ss = m0 * m0 + m1 * m1 + m2 * m2;
        #pragma unroll
        for (int o = 16; o; o >>= 1) ss += __shfl_xor_sync(0xffffffffu, ss, o);
        float mu0 = __shfl_sync(0xffffffffu, m0, 0);
        float neg = 2.0f * mu0 * mu0 - ss;
        float inv = rsqrtf(fmaxf(neg, EPS_)) * (1.0f / H_);
        a0 += m0 * inv; a1 += m1 * inv; a2 += m2 * inv;
    }
    float ss = a0 * a0 + a1 * a1 + a2 * a2;
    #pragma unroll
    for (int o = 16; o; o >>= 1) ss += __shfl_xor_sync(0xffffffffu, ss, o);
    float av0 = __shfl_sync(0xffffffffu, a0, 0);
    float neg = 2.0f * av0 * av0 - ss;
    float inv2 = rsqrtf(fmaxf(neg, EPS_));
    float sp0 = a0 * inv2, sp1 = a1 * inv2, sp2 = a2 * inv2;

    float ssp = sp1 * sp1 + ((lane == 0) ? sp2 * sp2 : sp0 * sp0);
    #pragma unroll
    for (int o = 16; o; o >>= 1) ssp += __shfl_xor_sync(0xffffffffu, ssp, o);
    float t = sqrtf(1.0f + ssp);

    float* o_ = out + ((size_t)b * N_ + n) * AD_;
    o_[lane]      = (lane == 0) ? t : sp0;
    o_[lane + 32] = sp1;
    if (lane == 0) o_[64] = sp2;
}

// ---------------- launch ------------------------------------------------------
extern "C" void kernel_launch(void* const* d_in, const int* in_sizes, int n_in,
                              void* d_out, int out_size)
{
    const float* x     = (const float*)d_in[0];
    const float* Wq    = (const float*)d_in[1];
    const float* Wk    = (const float*)d_in[2];
    const float* Wv    = (const float*)d_in[3];
    const float* bq    = (const float*)d_in[4];
    const float* bk    = (const float*)d_in[5];
    const float* bv    = (const float*)d_in[6];
    const float* scale = (const float*)d_in[7];
    float* out = (float*)d_out;

    cudaFuncSetAttribute(proj_kernel, cudaFuncAttributeMaxDynamicSharedMemorySize, PROJ_SMEM);
    cudaFuncSetAttribute(attn_kernel, cudaFuncAttributeMaxDynamicSharedMemorySize, ATTN_SMEM);

    prep_kernel<<<1024, 256>>>(x, Wq, Wk, Wv);
    proj_kernel<<<dim3(N_/128, 24, B_), 256, PROJ_SMEM>>>(bq, bk, bv);
    attn_kernel<<<dim3(N_/128, BH_), 256, ATTN_SMEM>>>(scale);
    finalize_kernel<<<(B_*N_*32 + 255)/256, 256>>>(out);
}